// round 12
// baseline (speedup 1.0000x reference)
#include <cuda_runtime.h>
#include <cuda_fp16.h>
#include <stdint.h>

#define NN      16384
#define EE      524288
#define DD      128
#define HH      256
#define CC      10
#define GG      64
#define WPR     512          // bitmask words per row (16384/32)
#define CAP     160          // max non-self neighbors per row

// ---------------- scratch (device globals; no allocation allowed) ----------------
__device__ uint32_t g_bm[(size_t)NN * WPR];        // 32 MB adjacency bitmask
__device__ int      g_nbr[(size_t)NN * CAP];       // CSR neighbor lists (unordered, no self)
__device__ int      g_cnt[NN];                     // per-row non-self neighbor counters
__device__ float    g_dis[NN];
__device__ __half   g_xh   [(size_t)NN * DD];      // half(dis[j]*x[j])
__device__ __half   g_agg1h[(size_t)NN * DD];
__device__ __half   g_hd1h [(size_t)NN * HH];      // half(dis*relu(.@W1+b1))
__device__ __half   g_agg2h[(size_t)NN * HH];
__device__ __half   g_h2h  [(size_t)NN * HH];      // half(relu(.@W2+b2))
__device__ __half   g_w1h[DD * HH];
__device__ __half   g_w2h[HH * HH];
__device__ int      g_segstart[GG + 1];

// ---------------- helpers ----------------
__device__ __forceinline__ uint32_t cvta_smem(const void* p) {
    return static_cast<uint32_t>(__cvta_generic_to_shared(p));
}
__device__ __forceinline__ void ldsm_x4(uint32_t (&r)[4], uint32_t addr) {
    asm volatile("ldmatrix.sync.aligned.m8n8.x4.shared.b16 {%0,%1,%2,%3}, [%4];"
                 : "=r"(r[0]), "=r"(r[1]), "=r"(r[2]), "=r"(r[3]) : "r"(addr));
}
__device__ __forceinline__ void ldsm_x4_t(uint32_t (&r)[4], uint32_t addr) {
    asm volatile("ldmatrix.sync.aligned.m8n8.x4.trans.shared.b16 {%0,%1,%2,%3}, [%4];"
                 : "=r"(r[0]), "=r"(r[1]), "=r"(r[2]), "=r"(r[3]) : "r"(addr));
}
__device__ __forceinline__ void mma16816(float (&d)[4], const uint32_t (&a)[4],
                                         const uint32_t b0, const uint32_t b1) {
    asm volatile("mma.sync.aligned.m16n8k16.row.col.f32.f16.f16.f32 "
                 "{%0,%1,%2,%3},{%4,%5,%6,%7},{%8,%9},{%0,%1,%2,%3};"
                 : "+f"(d[0]), "+f"(d[1]), "+f"(d[2]), "+f"(d[3])
                 : "r"(a[0]), "r"(a[1]), "r"(a[2]), "r"(a[3]), "r"(b0), "r"(b1));
}
__device__ __forceinline__ void cp_async16(void* smem, const void* gmem) {
    asm volatile("cp.async.cg.shared.global [%0], [%1], 16;"
                 :: "r"(cvta_smem(smem)), "l"(gmem));
}
__device__ __forceinline__ void cp_commit() {
    asm volatile("cp.async.commit_group;");
}
template <int N>
__device__ __forceinline__ void cp_wait() {
    asm volatile("cp.async.wait_group %0;" :: "n"(N));
}
__device__ __forceinline__ void acc_h2x2(float4& acc, uint2 raw) {
    float2 f0 = __half22float2(*reinterpret_cast<__half2*>(&raw.x));
    float2 f1 = __half22float2(*reinterpret_cast<__half2*>(&raw.y));
    acc.x += f0.x; acc.y += f0.y; acc.z += f1.x; acc.w += f1.y;
}
// PDL: sync on predecessor completion, then allow successor to launch.
__device__ __forceinline__ void pdl_sync_then_trigger() {
    cudaGridDependencySynchronize();
    cudaTriggerProgrammaticLaunchCompletion();
}

// ---------------- fused init (first kernel; no PDL needed) ----------------
__global__ void init_kernel(const float* __restrict__ W1, const float* __restrict__ W2,
                            const int* __restrict__ batch) {
    int gidx = blockIdx.x * blockDim.x + threadIdx.x;
    const int n4 = NN * WPR / 4;
    uint4 z = make_uint4(0, 0, 0, 0);
    for (int i = gidx; i < n4; i += gridDim.x * blockDim.x)
        reinterpret_cast<uint4*>(g_bm)[i] = z;
    if (gidx < DD * HH) g_w1h[gidx] = __float2half_rn(W1[gidx]);
    if (gidx < HH * HH) g_w2h[gidx] = __float2half_rn(W2[gidx]);
    if (gidx < NN) g_cnt[gidx] = 0;
    int g = gidx - 100000;
    if (g >= 0 && g <= GG) {
        if (g == GG) { g_segstart[GG] = NN; }
        else {
            int lo = 0, hi = NN;
            while (lo < hi) {
                int mid = (lo + hi) >> 1;
                if (batch[mid] < g) lo = mid + 1; else hi = mid;
            }
            g_segstart[g] = lo;
        }
    }
}

// ---------------- scatter + direct CSR build (dedup via atomicOr; self edges implicit) ----------------
__global__ void scatter_build_kernel(const int* __restrict__ ei) {
    int idx = blockIdx.x * blockDim.x + threadIdx.x;
    int s = 0, d = 0;
    bool act = idx < EE;
    if (act) {                         // prologue: input-only loads
        s = ei[idx];
        d = ei[EE + idx];
    }
    pdl_sync_then_trigger();           // wait init (zeroed bm/cnt)
    if (!act || s == d) return;        // self edges implicit
    uint32_t bit = 1u << (d & 31);
    uint32_t old = atomicOr(&g_bm[(size_t)s * WPR + (d >> 5)], bit);
    if (!(old & bit)) {
        int pos = atomicAdd(&g_cnt[s], 1);
        if (pos < CAP) g_nbr[(size_t)s * CAP + pos] = d;
    }
}

// dis[n] = rsqrt(cnt[n]+1);  xh[n][f] = half(dis[n]*x[n][f]) — 2 elems/thread, x preloaded
__global__ void finalize_x_kernel(const float* __restrict__ x) {
    const int HALFN2 = NN * DD / 4;    // 524288 = grid*block
    int i0 = blockIdx.x * blockDim.x + threadIdx.x;
    int i1 = i0 + HALFN2;
    const float2* x2 = reinterpret_cast<const float2*>(x);
    float2 v0 = x2[i0];                // prologue: input-only loads (overlaps scatter)
    float2 v1 = x2[i1];
    pdl_sync_then_trigger();           // wait scatter (g_cnt final)
    __half2* o2 = reinterpret_cast<__half2*>(g_xh);
    {
        int row = i0 >> 6;
        float s = rsqrtf((float)(g_cnt[row] + 1));
        if ((i0 & 63) == 0) g_dis[row] = s;
        o2[i0] = __float22half2_rn(make_float2(v0.x * s, v0.y * s));
    }
    {
        int row = i1 >> 6;
        float s = rsqrtf((float)(g_cnt[row] + 1));
        if ((i1 & 63) == 0) g_dis[row] = s;
        o2[i1] = __float22half2_rn(make_float2(v1.x * s, v1.y * s));
    }
}

// ---------------- gathers: shfl-broadcast indices, batch-8 consume, implicit self ----------------

// warp per row, D=128: lane handles 4 halves (8B/neighbor)
__global__ void agg1_kernel() {
    int row  = (blockIdx.x * blockDim.x + threadIdx.x) >> 5;
    int lane = threadIdx.x & 31;
    // prologue: cnt + indices come from scatter (>=2 kernels back => complete)
    int cnt = (row < NN) ? min(g_cnt[row], CAP) : 0;
    pdl_sync_then_trigger();           // wait finalize_x (xh, dis)
    if (row >= NN) return;
    const int* __restrict__ nbr = g_nbr + (size_t)row * CAP;
    const __half* __restrict__ xh = g_xh;
    float4 acc = make_float4(0.f, 0.f, 0.f, 0.f);
    acc_h2x2(acc, *reinterpret_cast<const uint2*>(xh + (size_t)row * DD + lane * 4));  // self
    for (int t0 = 0; t0 < cnt; t0 += 32) {
        int j = (t0 + lane < cnt) ? nbr[t0 + lane] : 0;
        int m = min(32, cnt - t0);
        if (m == 32) {
            #pragma unroll
            for (int kk = 0; kk < 32; kk += 8) {
                int jj[8];
                #pragma unroll
                for (int e = 0; e < 8; e++) jj[e] = __shfl_sync(0xFFFFFFFFu, j, kk + e);
                uint2 r[8];
                #pragma unroll
                for (int e = 0; e < 8; e++)
                    r[e] = *reinterpret_cast<const uint2*>(xh + (size_t)jj[e] * DD + lane * 4);
                #pragma unroll
                for (int e = 0; e < 8; e++) acc_h2x2(acc, r[e]);
            }
        } else {
            for (int k = 0; k < m; k++) {
                int jj = __shfl_sync(0xFFFFFFFFu, j, k);
                uint2 r = *reinterpret_cast<const uint2*>(xh + (size_t)jj * DD + lane * 4);
                acc_h2x2(acc, r);
            }
        }
    }
    float s = g_dis[row];
    __half2 h0 = __float22half2_rn(make_float2(acc.x * s, acc.y * s));
    __half2 h1 = __float22half2_rn(make_float2(acc.z * s, acc.w * s));
    uint2 packed = make_uint2(*reinterpret_cast<uint32_t*>(&h0), *reinterpret_cast<uint32_t*>(&h1));
    *reinterpret_cast<uint2*>(g_agg1h + (size_t)row * DD + lane * 4) = packed;
}

// 2 warps per row, H=256: each warp handles 128 halves (4/lane, 8B loads), batch-8
__global__ void agg2_kernel() {
    int gw   = (blockIdx.x * blockDim.x + threadIdx.x) >> 5;
    int lane = threadIdx.x & 31;
    int row  = gw >> 1;
    int half = gw & 1;
    // prologue: cnt/nbr from scatter, dis from finalize (>=2 back => complete)
    int cnt = (row < NN) ? min(g_cnt[row], CAP) : 0;
    float s = (row < NN) ? g_dis[row] : 0.f;
    pdl_sync_then_trigger();           // wait gemm1 (g_hd1h)
    if (row >= NN) return;
    const int* __restrict__ nbr = g_nbr + (size_t)row * CAP;
    const __half* __restrict__ hh = g_hd1h + half * 128 + lane * 4;
    float4 acc = make_float4(0.f, 0.f, 0.f, 0.f);
    acc_h2x2(acc, *reinterpret_cast<const uint2*>(hh + (size_t)row * HH));   // self
    for (int t0 = 0; t0 < cnt; t0 += 32) {
        int j = (t0 + lane < cnt) ? nbr[t0 + lane] : 0;
        int m = min(32, cnt - t0);
        if (m == 32) {
            #pragma unroll
            for (int kk = 0; kk < 32; kk += 8) {
                int jj[8];
                #pragma unroll
                for (int e = 0; e < 8; e++) jj[e] = __shfl_sync(0xFFFFFFFFu, j, kk + e);
                uint2 r[8];
                #pragma unroll
                for (int e = 0; e < 8; e++)
                    r[e] = *reinterpret_cast<const uint2*>(hh + (size_t)jj[e] * HH);
                #pragma unroll
                for (int e = 0; e < 8; e++) acc_h2x2(acc, r[e]);
            }
        } else {
            for (int k = 0; k < m; k++) {
                int jj = __shfl_sync(0xFFFFFFFFu, j, k);
                uint2 r = *reinterpret_cast<const uint2*>(hh + (size_t)jj * HH);
                acc_h2x2(acc, r);
            }
        }
    }
    __half2 h0 = __float22half2_rn(make_float2(acc.x * s, acc.y * s));
    __half2 h1 = __float22half2_rn(make_float2(acc.z * s, acc.w * s));
    uint2 packed = make_uint2(*reinterpret_cast<uint32_t*>(&h0), *reinterpret_cast<uint32_t*>(&h1));
    *reinterpret_cast<uint2*>(g_agg2h + (size_t)row * HH + half * 128 + lane * 4) = packed;
}

// ---------------- HMMA GEMM, double-buffered cp.async, PDL-prologued weight loads ----------------
template <int K, bool SCALE>
__global__ void __launch_bounds__(256, 2) hgemm_kernel(const __half* __restrict__ A,
                                                       const __half* __restrict__ W,
                                                       const float* __restrict__ bias,
                                                       __half* __restrict__ Ch) {
    __shared__ __half As[2][128][40];
    __shared__ __half Bs[2][32][136];

    const int tid  = threadIdx.x;
    const int lane = tid & 31;
    const int warp = tid >> 5;
    const int wm = warp & 3;
    const int wn = warp >> 2;
    const int rowBase = blockIdx.y * 128;
    const int colBase = blockIdx.x * 128;
    const int NITER = K / 32;

    const int ar = tid >> 1, ac = (tid & 1) * 16;
    const int br = tid >> 3, bc = (tid & 7) * 16;

    // prologue: weights come from init (>=2 kernels back => complete); bias is an input
    {
        const __half* bg = W + (size_t)br * 256 + colBase + bc;
        cp_async16(&Bs[0][br][bc],     bg);
        cp_async16(&Bs[0][br][bc + 8], bg + 8);
    }
    pdl_sync_then_trigger();           // wait predecessor (A operand producer)

    float acc[2][8][4];
    #pragma unroll
    for (int f = 0; f < 2; f++)
        #pragma unroll
        for (int t = 0; t < 8; t++)
            #pragma unroll
            for (int c = 0; c < 4; c++) acc[f][t][c] = 0.f;

    auto load_A = [&](int it, int buf) {
        const __half* ag = A + (size_t)(rowBase + ar) * K + it * 32 + ac;
        cp_async16(&As[buf][ar][ac],     ag);
        cp_async16(&As[buf][ar][ac + 8], ag + 8);
    };
    auto load_B = [&](int it, int buf) {
        const __half* bg = W + (size_t)(it * 32 + br) * 256 + colBase + bc;
        cp_async16(&Bs[buf][br][bc],     bg);
        cp_async16(&Bs[buf][br][bc + 8], bg + 8);
    };

    load_A(0, 0);
    cp_commit();
    cp_wait<0>();
    __syncthreads();

    for (int it = 0; it < NITER; it++) {
        int buf = it & 1;
        if (it + 1 < NITER) {
            load_A(it + 1, (it + 1) & 1);
            load_B(it + 1, (it + 1) & 1);
            cp_commit();
        }

        #pragma unroll
        for (int kk = 0; kk < 32; kk += 16) {
            uint32_t afr[2][4];
            #pragma unroll
            for (int f = 0; f < 2; f++)
                ldsm_x4(afr[f], cvta_smem(&As[buf][wm * 32 + f * 16 + (lane & 15)][kk + (lane >> 4) * 8]));
            uint32_t bfr[8][2];
            #pragma unroll
            for (int g = 0; g < 4; g++) {
                uint32_t t4[4];
                ldsm_x4_t(t4, cvta_smem(&Bs[buf][kk + (lane & 15)][wn * 64 + g * 16 + (lane >> 4) * 8]));
                bfr[2 * g][0] = t4[0]; bfr[2 * g][1] = t4[1];
                bfr[2 * g + 1][0] = t4[2]; bfr[2 * g + 1][1] = t4[3];
            }
            #pragma unroll
            for (int f = 0; f < 2; f++)
                #pragma unroll
                for (int t = 0; t < 8; t++)
                    mma16816(acc[f][t], afr[f], bfr[t][0], bfr[t][1]);
        }

        if (it + 1 < NITER) {
            cp_wait<0>();
            __syncthreads();
        }
    }

    #pragma unroll
    for (int f = 0; f < 2; f++) {
        #pragma unroll
        for (int t = 0; t < 8; t++) {
            int r0  = rowBase + wm * 32 + f * 16 + (lane >> 2);
            int col = colBase + wn * 64 + t * 8 + (lane & 3) * 2;
            float b0 = bias[col], b1 = bias[col + 1];
            #pragma unroll
            for (int h = 0; h < 2; h++) {
                int row = r0 + h * 8;
                float v0 = fmaxf(acc[f][t][h * 2 + 0] + b0, 0.f);
                float v1 = fmaxf(acc[f][t][h * 2 + 1] + b1, 0.f);
                if (SCALE) { float s = g_dis[row]; v0 *= s; v1 *= s; }
                *reinterpret_cast<__half2*>(Ch + (size_t)row * 256 + col) =
                    __float22half2_rn(make_float2(v0, v1));
            }
        }
    }
}

// ---------------- pooling / classifier (2-way unrolled sum) ----------------
__global__ void __launch_bounds__(256) pool_classify_kernel(const float* __restrict__ Wc,
                                                            const float* __restrict__ bc,
                                                            float* __restrict__ out) {
    int g = blockIdx.x;
    int t = threadIdx.x;
    int s = g_segstart[g], e = g_segstart[g + 1];   // prologue: init output (>=2 back)
    const float* wr = Wc + t * CC;
    float w[CC];
    #pragma unroll
    for (int c = 0; c < CC; c++) w[c] = wr[c];      // prologue: input
    pdl_sync_then_trigger();                        // wait gemm2 (g_h2h)
    float sum0 = 0.f, sum1 = 0.f;
    int n = s;
    for (; n + 1 < e; n += 2) {
        sum0 += __half2float(g_h2h[(size_t)n * HH + t]);
        sum1 += __half2float(g_h2h[(size_t)(n + 1) * HH + t]);
    }
    if (n < e) sum0 += __half2float(g_h2h[(size_t)n * HH + t]);
    float cnt = (float)max(e - s, 1);
    float pv = (sum0 + sum1) / cnt;

    float part[CC];
    #pragma unroll
    for (int c = 0; c < CC; c++) part[c] = pv * w[c];
    #pragma unroll
    for (int o = 16; o > 0; o >>= 1)
        #pragma unroll
        for (int c = 0; c < CC; c++) part[c] += __shfl_down_sync(0xFFFFFFFFu, part[c], o);

    __shared__ float red[8][CC];
    if ((t & 31) == 0)
        #pragma unroll
        for (int c = 0; c < CC; c++) red[t >> 5][c] = part[c];
    __syncthreads();
    if (t < CC) {
        float o = bc[t];
        #pragma unroll
        for (int wv = 0; wv < 8; wv++) o += red[wv][t];
        out[g * CC + t] = o;
    }
}

// ---------------- launch (PDL chain) ----------------
template <typename Kern, typename... Args>
static void launch_pdl(Kern k, dim3 grid, dim3 block, Args... args) {
    cudaLaunchConfig_t cfg = {};
    cfg.gridDim = grid;
    cfg.blockDim = block;
    cfg.dynamicSmemBytes = 0;
    cfg.stream = 0;
    cudaLaunchAttribute attr[1];
    attr[0].id = cudaLaunchAttributeProgrammaticStreamSerialization;
    attr[0].val.programmaticStreamSerializationAllowed = 1;
    cfg.attrs = attr;
    cfg.numAttrs = 1;
    cudaLaunchKernelEx(&cfg, k, args...);
}

extern "C" void kernel_launch(void* const* d_in, const int* in_sizes, int n_in,
                              void* d_out, int out_size) {
    const float* x   = (const float*)d_in[0];
    const int*   ei  = (const int*)  d_in[1];
    const int*   bat = (const int*)  d_in[2];
    const float* W1  = (const float*)d_in[3];
    const float* b1  = (const float*)d_in[4];
    const float* W2  = (const float*)d_in[5];
    const float* b2  = (const float*)d_in[6];
    const float* Wc  = (const float*)d_in[7];
    const float* bc  = (const float*)d_in[8];
    float* out = (float*)d_out;

    __half *w1h, *w2h, *agg1h, *agg2h, *hd1h, *h2h;
    cudaGetSymbolAddress((void**)&w1h,   g_w1h);
    cudaGetSymbolAddress((void**)&w2h,   g_w2h);
    cudaGetSymbolAddress((void**)&agg1h, g_agg1h);
    cudaGetSymbolAddress((void**)&agg2h, g_agg2h);
    cudaGetSymbolAddress((void**)&hd1h,  g_hd1h);
    cudaGetSymbolAddress((void**)&h2h,   g_h2h);

    init_kernel<<<2048, 256>>>(W1, W2, bat);
    launch_pdl(scatter_build_kernel, dim3((EE + 255) / 256), dim3(256), ei);
    launch_pdl(finalize_x_kernel, dim3(2048), dim3(256), x);
    launch_pdl(agg1_kernel, dim3(NN / 8), dim3(256));
    launch_pdl(hgemm_kernel<DD, true>, dim3(2, 128), dim3(256),
               (const __half*)agg1h, (const __half*)w1h, b1, hd1h);
    launch_pdl(agg2_kernel, dim3(NN / 4), dim3(256));
    launch_pdl(hgemm_kernel<HH, false>, dim3(2, 128), dim3(256),
               (const __half*)agg2h, (const __half*)w2h, b2, h2h);
    launch_pdl(pool_classify_kernel, dim3(GG), dim3(256), Wc, bc, out);
}

// round 13
// speedup vs baseline: 1.1428x; 1.1428x over previous
#include <cuda_runtime.h>
#include <cuda_fp16.h>
#include <stdint.h>

#define NN      16384
#define EE      524288
#define DD      128
#define HH      256
#define CC      10
#define GG      64
#define WPR     512          // bitmask words per row (16384/32)
#define CAP     160          // max non-self neighbors per row

// ---------------- scratch (device globals; no allocation allowed) ----------------
// INVARIANT: g_bm and g_cnt are all-zero at entry of every kernel_launch call.
// (zero-initialized at module load; agg1 clears bm bits, pool resets cnt.)
__device__ uint32_t g_bm[(size_t)NN * WPR];        // 32 MB adjacency bitmask
__device__ int      g_nbr[(size_t)NN * CAP];       // CSR neighbor lists (unordered, no self)
__device__ int      g_cnt[NN];                     // per-row non-self neighbor counters
__device__ float    g_dis[NN];
__device__ __half   g_xh   [(size_t)NN * DD];      // half(dis[j]*x[j])
__device__ __half   g_agg1h[(size_t)NN * DD];
__device__ __half   g_hd1h [(size_t)NN * HH];      // half(dis*relu(.@W1+b1))
__device__ __half   g_agg2h[(size_t)NN * HH];
__device__ __half   g_h2h  [(size_t)NN * HH];      // half(relu(.@W2+b2))
__device__ __half   g_w1h[DD * HH];
__device__ __half   g_w2h[HH * HH];
__device__ int      g_segstart[GG + 1];

// ---------------- helpers ----------------
__device__ __forceinline__ uint32_t cvta_smem(const void* p) {
    return static_cast<uint32_t>(__cvta_generic_to_shared(p));
}
__device__ __forceinline__ void ldsm_x4(uint32_t (&r)[4], uint32_t addr) {
    asm volatile("ldmatrix.sync.aligned.m8n8.x4.shared.b16 {%0,%1,%2,%3}, [%4];"
                 : "=r"(r[0]), "=r"(r[1]), "=r"(r[2]), "=r"(r[3]) : "r"(addr));
}
__device__ __forceinline__ void ldsm_x4_t(uint32_t (&r)[4], uint32_t addr) {
    asm volatile("ldmatrix.sync.aligned.m8n8.x4.trans.shared.b16 {%0,%1,%2,%3}, [%4];"
                 : "=r"(r[0]), "=r"(r[1]), "=r"(r[2]), "=r"(r[3]) : "r"(addr));
}
__device__ __forceinline__ void mma16816(float (&d)[4], const uint32_t (&a)[4],
                                         const uint32_t b0, const uint32_t b1) {
    asm volatile("mma.sync.aligned.m16n8k16.row.col.f32.f16.f16.f32 "
                 "{%0,%1,%2,%3},{%4,%5,%6,%7},{%8,%9},{%0,%1,%2,%3};"
                 : "+f"(d[0]), "+f"(d[1]), "+f"(d[2]), "+f"(d[3])
                 : "r"(a[0]), "r"(a[1]), "r"(a[2]), "r"(a[3]), "r"(b0), "r"(b1));
}
__device__ __forceinline__ void cp_async16(void* smem, const void* gmem) {
    asm volatile("cp.async.cg.shared.global [%0], [%1], 16;"
                 :: "r"(cvta_smem(smem)), "l"(gmem));
}
__device__ __forceinline__ void cp_commit() {
    asm volatile("cp.async.commit_group;");
}
template <int N>
__device__ __forceinline__ void cp_wait() {
    asm volatile("cp.async.wait_group %0;" :: "n"(N));
}
__device__ __forceinline__ void acc_h2x2(float4& acc, uint2 raw) {
    float2 f0 = __half22float2(*reinterpret_cast<__half2*>(&raw.x));
    float2 f1 = __half22float2(*reinterpret_cast<__half2*>(&raw.y));
    acc.x += f0.x; acc.y += f0.y; acc.z += f1.x; acc.w += f1.y;
}
__device__ __forceinline__ void acc_h2x4(float4& a0, float4& a1, uint4 raw) {
    float2 f0 = __half22float2(*reinterpret_cast<__half2*>(&raw.x));
    float2 f1 = __half22float2(*reinterpret_cast<__half2*>(&raw.y));
    float2 f2 = __half22float2(*reinterpret_cast<__half2*>(&raw.z));
    float2 f3 = __half22float2(*reinterpret_cast<__half2*>(&raw.w));
    a0.x += f0.x; a0.y += f0.y; a0.z += f1.x; a0.w += f1.y;
    a1.x += f2.x; a1.y += f2.y; a1.z += f3.x; a1.w += f3.y;
}

// ---------------- init: weights + segstart only (no 32MB zero!) ----------------
__global__ void init_kernel(const float* __restrict__ W1, const float* __restrict__ W2,
                            const int* __restrict__ batch) {
    int gidx = blockIdx.x * blockDim.x + threadIdx.x;   // 384*256 = 98304 threads
    if (gidx < DD * HH) g_w1h[gidx] = __float2half_rn(W1[gidx]);
    if (gidx < HH * HH) g_w2h[gidx] = __float2half_rn(W2[gidx]);
    int g = gidx - 70000;
    if (g >= 0 && g <= GG) {
        if (g == GG) { g_segstart[GG] = NN; }
        else {
            int lo = 0, hi = NN;
            while (lo < hi) {
                int mid = (lo + hi) >> 1;
                if (batch[mid] < g) lo = mid + 1; else hi = mid;
            }
            g_segstart[g] = lo;
        }
    }
}

// ---------------- scatter + direct CSR build (dedup via atomicOr; self edges implicit) ----------------
__global__ void scatter_build_kernel(const int* __restrict__ ei) {
    int idx = blockIdx.x * blockDim.x + threadIdx.x;
    if (idx >= EE) return;
    int s = ei[idx];
    int d = ei[EE + idx];
    if (s == d) return;               // covered by the implicit self-loop
    uint32_t bit = 1u << (d & 31);
    uint32_t old = atomicOr(&g_bm[(size_t)s * WPR + (d >> 5)], bit);
    if (!(old & bit)) {
        int pos = atomicAdd(&g_cnt[s], 1);
        if (pos < CAP) g_nbr[(size_t)s * CAP + pos] = d;
    }
}

// dis[n] = rsqrt(cnt[n]+1);  xh[n][f] = half(dis[n]*x[n][f])
__global__ void finalize_x_kernel(const float* __restrict__ x) {
    const int n2 = NN * DD / 2;
    const float2* x2 = reinterpret_cast<const float2*>(x);
    __half2* o2 = reinterpret_cast<__half2*>(g_xh);
    for (int i = blockIdx.x * blockDim.x + threadIdx.x; i < n2; i += gridDim.x * blockDim.x) {
        int row = i >> 6;
        float s = rsqrtf((float)(g_cnt[row] + 1));
        if ((i & 63) == 0) g_dis[row] = s;
        float2 v = x2[i];
        o2[i] = __float22half2_rn(make_float2(v.x * s, v.y * s));
    }
}

// ---------------- agg1: paired-lane gather (2 neighbors/step, 16B loads) + bm clear ----------------
// warp per row; lanes 0-15 cover features of even pair member, 16-31 of odd member.
__global__ void agg1_kernel() {
    int row  = (blockIdx.x * blockDim.x + threadIdx.x) >> 5;
    int lane = threadIdx.x & 31;
    if (row >= NN) return;
    const int* __restrict__ nbr = g_nbr + (size_t)row * CAP;
    int cnt = min(g_cnt[row], CAP);
    const __half* __restrict__ xh = g_xh;
    const int fl = (lane & 15) * 8;   // feature offset (8 halves per lane)
    const int hi = lane >> 4;         // which member of the neighbor pair
    float4 a0 = make_float4(0.f, 0.f, 0.f, 0.f);
    float4 a1 = make_float4(0.f, 0.f, 0.f, 0.f);
    for (int t0 = 0; t0 < cnt; t0 += 32) {
        int j = (t0 + lane < cnt) ? nbr[t0 + lane] : 0;
        int m = min(32, cnt - t0);
        if (m == 32) {
            #pragma unroll
            for (int kk = 0; kk < 32; kk += 16) {   // 16 neighbors per sub-batch, 8 steps
                int jj[8];
                #pragma unroll
                for (int e = 0; e < 8; e++)
                    jj[e] = __shfl_sync(0xFFFFFFFFu, j, kk + 2 * e + hi);
                uint4 r[8];
                #pragma unroll
                for (int e = 0; e < 8; e++)
                    r[e] = *reinterpret_cast<const uint4*>(xh + (size_t)jj[e] * DD + fl);
                #pragma unroll
                for (int e = 0; e < 8; e++) acc_h2x4(a0, a1, r[e]);
            }
        } else {
            int k = 0;
            for (; k + 1 < m; k += 2) {
                int jj = __shfl_sync(0xFFFFFFFFu, j, k + hi);
                uint4 r = *reinterpret_cast<const uint4*>(xh + (size_t)jj * DD + fl);
                acc_h2x4(a0, a1, r);
            }
            if (k < m) {               // odd tail: only hi==0 half accumulates
                int jj = __shfl_sync(0xFFFFFFFFu, j, k);
                if (hi == 0) {
                    uint4 r = *reinterpret_cast<const uint4*>(xh + (size_t)jj * DD + fl);
                    acc_h2x4(a0, a1, r);
                }
            }
        }
    }
    // combine the two halves (xor 16): afterwards every lane holds the full neighbor sum
    a0.x += __shfl_xor_sync(0xFFFFFFFFu, a0.x, 16);
    a0.y += __shfl_xor_sync(0xFFFFFFFFu, a0.y, 16);
    a0.z += __shfl_xor_sync(0xFFFFFFFFu, a0.z, 16);
    a0.w += __shfl_xor_sync(0xFFFFFFFFu, a0.w, 16);
    a1.x += __shfl_xor_sync(0xFFFFFFFFu, a1.x, 16);
    a1.y += __shfl_xor_sync(0xFFFFFFFFu, a1.y, 16);
    a1.z += __shfl_xor_sync(0xFFFFFFFFu, a1.z, 16);
    a1.w += __shfl_xor_sync(0xFFFFFFFFu, a1.w, 16);
    // implicit self-loop contribution (added once, after reduction)
    acc_h2x4(a0, a1, *reinterpret_cast<const uint4*>(xh + (size_t)row * DD + fl));
    float s = g_dis[row];
    if (hi == 0) {
        __half2 h0 = __float22half2_rn(make_float2(a0.x * s, a0.y * s));
        __half2 h1 = __float22half2_rn(make_float2(a0.z * s, a0.w * s));
        __half2 h2 = __float22half2_rn(make_float2(a1.x * s, a1.y * s));
        __half2 h3 = __float22half2_rn(make_float2(a1.z * s, a1.w * s));
        uint4 p = make_uint4(*reinterpret_cast<uint32_t*>(&h0), *reinterpret_cast<uint32_t*>(&h1),
                             *reinterpret_cast<uint32_t*>(&h2), *reinterpret_cast<uint32_t*>(&h3));
        *reinterpret_cast<uint4*>(g_agg1h + (size_t)row * DD + fl) = p;
    }
    // clear this row's bitmask bits (row-private; idempotent stores) -> bm zero for next call
    for (int t = lane; t < cnt; t += 32)
        g_bm[(size_t)row * WPR + (nbr[t] >> 5)] = 0u;
}

// 2 warps per row, H=256: each warp handles 128 halves (4/lane, 8B loads), batch-8
__global__ void agg2_kernel() {
    int gw   = (blockIdx.x * blockDim.x + threadIdx.x) >> 5;
    int lane = threadIdx.x & 31;
    int row  = gw >> 1;
    int half = gw & 1;
    if (row >= NN) return;
    const int* __restrict__ nbr = g_nbr + (size_t)row * CAP;
    int cnt = min(g_cnt[row], CAP);
    const __half* __restrict__ hh = g_hd1h + half * 128 + lane * 4;
    float4 acc = make_float4(0.f, 0.f, 0.f, 0.f);
    acc_h2x2(acc, *reinterpret_cast<const uint2*>(hh + (size_t)row * HH));   // self
    for (int t0 = 0; t0 < cnt; t0 += 32) {
        int j = (t0 + lane < cnt) ? nbr[t0 + lane] : 0;
        int m = min(32, cnt - t0);
        if (m == 32) {
            #pragma unroll
            for (int kk = 0; kk < 32; kk += 8) {
                int jj[8];
                #pragma unroll
                for (int e = 0; e < 8; e++) jj[e] = __shfl_sync(0xFFFFFFFFu, j, kk + e);
                uint2 r[8];
                #pragma unroll
                for (int e = 0; e < 8; e++)
                    r[e] = *reinterpret_cast<const uint2*>(hh + (size_t)jj[e] * HH);
                #pragma unroll
                for (int e = 0; e < 8; e++) acc_h2x2(acc, r[e]);
            }
        } else {
            for (int k = 0; k < m; k++) {
                int jj = __shfl_sync(0xFFFFFFFFu, j, k);
                uint2 r = *reinterpret_cast<const uint2*>(hh + (size_t)jj * HH);
                acc_h2x2(acc, r);
            }
        }
    }
    float s = g_dis[row];
    __half2 h0 = __float22half2_rn(make_float2(acc.x * s, acc.y * s));
    __half2 h1 = __float22half2_rn(make_float2(acc.z * s, acc.w * s));
    uint2 packed = make_uint2(*reinterpret_cast<uint32_t*>(&h0), *reinterpret_cast<uint32_t*>(&h1));
    *reinterpret_cast<uint2*>(g_agg2h + (size_t)row * HH + half * 128 + lane * 4) = packed;
}

// ---------------- HMMA GEMM, double-buffered cp.async: 128x128 tile, 8 warps, BK=32 ----------------
template <int K, bool SCALE>
__global__ void __launch_bounds__(256, 2) hgemm_kernel(const __half* __restrict__ A,
                                                       const __half* __restrict__ W,
                                                       const float* __restrict__ bias,
                                                       __half* __restrict__ Ch) {
    __shared__ __half As[2][128][40];
    __shared__ __half Bs[2][32][136];

    const int tid  = threadIdx.x;
    const int lane = tid & 31;
    const int warp = tid >> 5;
    const int wm = warp & 3;
    const int wn = warp >> 2;
    const int rowBase = blockIdx.y * 128;
    const int colBase = blockIdx.x * 128;
    const int NITER = K / 32;

    float acc[2][8][4];
    #pragma unroll
    for (int f = 0; f < 2; f++)
        #pragma unroll
        for (int t = 0; t < 8; t++)
            #pragma unroll
            for (int c = 0; c < 4; c++) acc[f][t][c] = 0.f;

    const int ar = tid >> 1, ac = (tid & 1) * 16;
    const int br = tid >> 3, bc = (tid & 7) * 16;

    auto load_tile = [&](int it, int buf) {
        const __half* ag = A + (size_t)(rowBase + ar) * K + it * 32 + ac;
        cp_async16(&As[buf][ar][ac],     ag);
        cp_async16(&As[buf][ar][ac + 8], ag + 8);
        const __half* bg = W + (size_t)(it * 32 + br) * 256 + colBase + bc;
        cp_async16(&Bs[buf][br][bc],     bg);
        cp_async16(&Bs[buf][br][bc + 8], bg + 8);
        cp_commit();
    };

    load_tile(0, 0);
    cp_wait<0>();
    __syncthreads();

    for (int it = 0; it < NITER; it++) {
        int buf = it & 1;
        if (it + 1 < NITER) load_tile(it + 1, (it + 1) & 1);

        #pragma unroll
        for (int kk = 0; kk < 32; kk += 16) {
            uint32_t afr[2][4];
            #pragma unroll
            for (int f = 0; f < 2; f++)
                ldsm_x4(afr[f], cvta_smem(&As[buf][wm * 32 + f * 16 + (lane & 15)][kk + (lane >> 4) * 8]));
            uint32_t bfr[8][2];
            #pragma unroll
            for (int g = 0; g < 4; g++) {
                uint32_t t4[4];
                ldsm_x4_t(t4, cvta_smem(&Bs[buf][kk + (lane & 15)][wn * 64 + g * 16 + (lane >> 4) * 8]));
                bfr[2 * g][0] = t4[0]; bfr[2 * g][1] = t4[1];
                bfr[2 * g + 1][0] = t4[2]; bfr[2 * g + 1][1] = t4[3];
            }
            #pragma unroll
            for (int f = 0; f < 2; f++)
                #pragma unroll
                for (int t = 0; t < 8; t++)
                    mma16816(acc[f][t], afr[f], bfr[t][0], bfr[t][1]);
        }

        if (it + 1 < NITER) {
            cp_wait<0>();
            __syncthreads();
        }
    }

    #pragma unroll
    for (int f = 0; f < 2; f++) {
        #pragma unroll
        for (int t = 0; t < 8; t++) {
            int r0  = rowBase + wm * 32 + f * 16 + (lane >> 2);
            int col = colBase + wn * 64 + t * 8 + (lane & 3) * 2;
            float b0 = bias[col], b1 = bias[col + 1];
            #pragma unroll
            for (int h = 0; h < 2; h++) {
                int row = r0 + h * 8;
                float v0 = fmaxf(acc[f][t][h * 2 + 0] + b0, 0.f);
                float v1 = fmaxf(acc[f][t][h * 2 + 1] + b1, 0.f);
                if (SCALE) { float s = g_dis[row]; v0 *= s; v1 *= s; }
                *reinterpret_cast<__half2*>(Ch + (size_t)row * 256 + col) =
                    __float22half2_rn(make_float2(v0, v1));
            }
        }
    }
}

// ---------------- pooling / classifier + g_cnt reset (64*256 threads == NN) ----------------
__global__ void __launch_bounds__(256) pool_classify_kernel(const float* __restrict__ Wc,
                                                            const float* __restrict__ bc,
                                                            float* __restrict__ out) {
    int g = blockIdx.x;
    int t = threadIdx.x;
    g_cnt[g * 256 + t] = 0;            // restore invariant for the next call
    int s = g_segstart[g], e = g_segstart[g + 1];
    float sum0 = 0.f, sum1 = 0.f;
    int n = s;
    for (; n + 1 < e; n += 2) {
        sum0 += __half2float(g_h2h[(size_t)n * HH + t]);
        sum1 += __half2float(g_h2h[(size_t)(n + 1) * HH + t]);
    }
    if (n < e) sum0 += __half2float(g_h2h[(size_t)n * HH + t]);
    float cnt = (float)max(e - s, 1);
    float pv = (sum0 + sum1) / cnt;

    float part[CC];
    const float* wr = Wc + t * CC;
    #pragma unroll
    for (int c = 0; c < CC; c++) part[c] = pv * wr[c];
    #pragma unroll
    for (int o = 16; o > 0; o >>= 1)
        #pragma unroll
        for (int c = 0; c < CC; c++) part[c] += __shfl_down_sync(0xFFFFFFFFu, part[c], o);

    __shared__ float red[8][CC];
    if ((t & 31) == 0)
        #pragma unroll
        for (int c = 0; c < CC; c++) red[t >> 5][c] = part[c];
    __syncthreads();
    if (t < CC) {
        float o = bc[t];
        #pragma unroll
        for (int w = 0; w < 8; w++) o += red[w][t];
        out[g * CC + t] = o;
    }
}

// ---------------- launch ----------------
extern "C" void kernel_launch(void* const* d_in, const int* in_sizes, int n_in,
                              void* d_out, int out_size) {
    const float* x   = (const float*)d_in[0];
    const int*   ei  = (const int*)  d_in[1];
    const int*   bat = (const int*)  d_in[2];
    const float* W1  = (const float*)d_in[3];
    const float* b1  = (const float*)d_in[4];
    const float* W2  = (const float*)d_in[5];
    const float* b2  = (const float*)d_in[6];
    const float* Wc  = (const float*)d_in[7];
    const float* bc  = (const float*)d_in[8];
    float* out = (float*)d_out;

    __half *w1h, *w2h, *agg1h, *agg2h, *hd1h, *h2h;
    cudaGetSymbolAddress((void**)&w1h,   g_w1h);
    cudaGetSymbolAddress((void**)&w2h,   g_w2h);
    cudaGetSymbolAddress((void**)&agg1h, g_agg1h);
    cudaGetSymbolAddress((void**)&agg2h, g_agg2h);
    cudaGetSymbolAddress((void**)&hd1h,  g_hd1h);
    cudaGetSymbolAddress((void**)&h2h,   g_h2h);

    init_kernel<<<384, 256>>>(W1, W2, bat);
    scatter_build_kernel<<<(EE + 255) / 256, 256>>>(ei);
    finalize_x_kernel<<<2048, 256>>>(x);
    agg1_kernel<<<NN / 8, 256>>>();
    hgemm_kernel<DD, true><<<dim3(2, 128), 256>>>(agg1h, w1h, b1, hd1h);
    agg2_kernel<<<NN / 4, 256>>>();
    hgemm_kernel<HH, false><<<dim3(2, 128), 256>>>(agg2h, w2h, b2, h2h);
    pool_classify_kernel<<<GG, 256>>>(Wc, bc, out);
}

// round 14
// speedup vs baseline: 1.1666x; 1.0208x over previous
#include <cuda_runtime.h>
#include <cuda_fp16.h>
#include <stdint.h>

#define NN      16384
#define EE      524288
#define DD      128
#define HH      256
#define CC      10
#define GG      64
#define WPR     512          // bitmask words per row (16384/32)
#define CAP     160          // max non-self neighbors per row

// ---------------- scratch (device globals; no allocation allowed) ----------------
// INVARIANT: g_bm and g_cnt are all-zero at entry of every kernel_launch call.
// (zero-initialized at module load; agg1 clears bm bits, pool resets cnt.)
__device__ uint32_t g_bm[(size_t)NN * WPR];        // 32 MB adjacency bitmask
__device__ int      g_nbr[(size_t)NN * CAP];       // CSR neighbor lists (unordered, no self)
__device__ int      g_cnt[NN];                     // per-row non-self neighbor counters
__device__ float    g_dis[NN];
__device__ __half   g_xh   [(size_t)NN * DD];      // half(dis[j]*x[j])
__device__ __half   g_agg1h[(size_t)NN * DD];
__device__ __half   g_hd1h [(size_t)NN * HH];      // half(dis*relu(.@W1+b1))
__device__ __half   g_agg2h[(size_t)NN * HH];
__device__ __half   g_h2h  [(size_t)NN * HH];      // half(relu(.@W2+b2))
__device__ __half   g_w1h[DD * HH];
__device__ __half   g_w2h[HH * HH];
__device__ int      g_segstart[GG + 1];

// ---------------- helpers ----------------
__device__ __forceinline__ uint32_t cvta_smem(const void* p) {
    return static_cast<uint32_t>(__cvta_generic_to_shared(p));
}
__device__ __forceinline__ void ldsm_x4(uint32_t (&r)[4], uint32_t addr) {
    asm volatile("ldmatrix.sync.aligned.m8n8.x4.shared.b16 {%0,%1,%2,%3}, [%4];"
                 : "=r"(r[0]), "=r"(r[1]), "=r"(r[2]), "=r"(r[3]) : "r"(addr));
}
__device__ __forceinline__ void ldsm_x4_t(uint32_t (&r)[4], uint32_t addr) {
    asm volatile("ldmatrix.sync.aligned.m8n8.x4.trans.shared.b16 {%0,%1,%2,%3}, [%4];"
                 : "=r"(r[0]), "=r"(r[1]), "=r"(r[2]), "=r"(r[3]) : "r"(addr));
}
__device__ __forceinline__ void mma16816(float (&d)[4], const uint32_t (&a)[4],
                                         const uint32_t b0, const uint32_t b1) {
    asm volatile("mma.sync.aligned.m16n8k16.row.col.f32.f16.f16.f32 "
                 "{%0,%1,%2,%3},{%4,%5,%6,%7},{%8,%9},{%0,%1,%2,%3};"
                 : "+f"(d[0]), "+f"(d[1]), "+f"(d[2]), "+f"(d[3])
                 : "r"(a[0]), "r"(a[1]), "r"(a[2]), "r"(a[3]), "r"(b0), "r"(b1));
}
__device__ __forceinline__ void cp_async16(void* smem, const void* gmem) {
    asm volatile("cp.async.cg.shared.global [%0], [%1], 16;"
                 :: "r"(cvta_smem(smem)), "l"(gmem));
}
__device__ __forceinline__ void cp_commit() {
    asm volatile("cp.async.commit_group;");
}
template <int N>
__device__ __forceinline__ void cp_wait() {
    asm volatile("cp.async.wait_group %0;" :: "n"(N));
}
__device__ __forceinline__ void acc_h2x2(float4& acc, uint2 raw) {
    float2 f0 = __half22float2(*reinterpret_cast<__half2*>(&raw.x));
    float2 f1 = __half22float2(*reinterpret_cast<__half2*>(&raw.y));
    acc.x += f0.x; acc.y += f0.y; acc.z += f1.x; acc.w += f1.y;
}

// ---------------- init: weights + segstart only (no 32MB zero!) ----------------
__global__ void init_kernel(const float* __restrict__ W1, const float* __restrict__ W2,
                            const int* __restrict__ batch) {
    int gidx = blockIdx.x * blockDim.x + threadIdx.x;   // 384*256 = 98304 threads
    if (gidx < DD * HH) g_w1h[gidx] = __float2half_rn(W1[gidx]);
    if (gidx < HH * HH) g_w2h[gidx] = __float2half_rn(W2[gidx]);
    int g = gidx - 70000;
    if (g >= 0 && g <= GG) {
        if (g == GG) { g_segstart[GG] = NN; }
        else {
            int lo = 0, hi = NN;
            while (lo < hi) {
                int mid = (lo + hi) >> 1;
                if (batch[mid] < g) lo = mid + 1; else hi = mid;
            }
            g_segstart[g] = lo;
        }
    }
}

// ---------------- scatter + direct CSR build (dedup via atomicOr; self edges implicit) ----------------
__global__ void scatter_build_kernel(const int* __restrict__ ei) {
    int idx = blockIdx.x * blockDim.x + threadIdx.x;
    if (idx >= EE) return;
    int s = ei[idx];
    int d = ei[EE + idx];
    if (s == d) return;               // covered by the implicit self-loop
    uint32_t bit = 1u << (d & 31);
    uint32_t old = atomicOr(&g_bm[(size_t)s * WPR + (d >> 5)], bit);
    if (!(old & bit)) {
        int pos = atomicAdd(&g_cnt[s], 1);
        if (pos < CAP) g_nbr[(size_t)s * CAP + pos] = d;
    }
}

// dis[n] = rsqrt(cnt[n]+1);  xh[n][f] = half(dis[n]*x[n][f])
__global__ void finalize_x_kernel(const float* __restrict__ x) {
    const int n2 = NN * DD / 2;
    const float2* x2 = reinterpret_cast<const float2*>(x);
    __half2* o2 = reinterpret_cast<__half2*>(g_xh);
    for (int i = blockIdx.x * blockDim.x + threadIdx.x; i < n2; i += gridDim.x * blockDim.x) {
        int row = i >> 6;
        float s = rsqrtf((float)(g_cnt[row] + 1));
        if ((i & 63) == 0) g_dis[row] = s;
        float2 v = x2[i];
        o2[i] = __float22half2_rn(make_float2(v.x * s, v.y * s));
    }
}

// ---------------- agg1: warp/row, batch-8 uint2 gather, implicit self, + bm clear ----------------
__global__ void agg1_kernel() {
    int row  = (blockIdx.x * blockDim.x + threadIdx.x) >> 5;
    int lane = threadIdx.x & 31;
    if (row >= NN) return;
    const int* __restrict__ nbr = g_nbr + (size_t)row * CAP;
    int cnt = min(g_cnt[row], CAP);
    const __half* __restrict__ xh = g_xh;
    float4 acc = make_float4(0.f, 0.f, 0.f, 0.f);
    acc_h2x2(acc, *reinterpret_cast<const uint2*>(xh + (size_t)row * DD + lane * 4));  // self
    for (int t0 = 0; t0 < cnt; t0 += 32) {
        int j = (t0 + lane < cnt) ? nbr[t0 + lane] : 0;
        int m = min(32, cnt - t0);
        if (m == 32) {
            #pragma unroll
            for (int kk = 0; kk < 32; kk += 8) {
                int jj[8];
                #pragma unroll
                for (int e = 0; e < 8; e++) jj[e] = __shfl_sync(0xFFFFFFFFu, j, kk + e);
                uint2 r[8];
                #pragma unroll
                for (int e = 0; e < 8; e++)
                    r[e] = *reinterpret_cast<const uint2*>(xh + (size_t)jj[e] * DD + lane * 4);
                #pragma unroll
                for (int e = 0; e < 8; e++) acc_h2x2(acc, r[e]);
            }
        } else {
            for (int k = 0; k < m; k++) {
                int jj = __shfl_sync(0xFFFFFFFFu, j, k);
                uint2 r = *reinterpret_cast<const uint2*>(xh + (size_t)jj * DD + lane * 4);
                acc_h2x2(acc, r);
            }
        }
    }
    float s = g_dis[row];
    __half2 h0 = __float22half2_rn(make_float2(acc.x * s, acc.y * s));
    __half2 h1 = __float22half2_rn(make_float2(acc.z * s, acc.w * s));
    uint2 packed = make_uint2(*reinterpret_cast<uint32_t*>(&h0), *reinterpret_cast<uint32_t*>(&h1));
    *reinterpret_cast<uint2*>(g_agg1h + (size_t)row * DD + lane * 4) = packed;
    // clear this row's bitmask bits (row-private; idempotent stores) -> bm zero for next call
    for (int t = lane; t < cnt; t += 32)
        g_bm[(size_t)row * WPR + (nbr[t] >> 5)] = 0u;
}

// 2 warps per row, H=256: each warp handles 128 halves (4/lane, 8B loads), batch-8
__global__ void agg2_kernel() {
    int gw   = (blockIdx.x * blockDim.x + threadIdx.x) >> 5;
    int lane = threadIdx.x & 31;
    int row  = gw >> 1;
    int half = gw & 1;
    if (row >= NN) return;
    const int* __restrict__ nbr = g_nbr + (size_t)row * CAP;
    int cnt = min(g_cnt[row], CAP);
    const __half* __restrict__ hh = g_hd1h + half * 128 + lane * 4;
    float4 acc = make_float4(0.f, 0.f, 0.f, 0.f);
    acc_h2x2(acc, *reinterpret_cast<const uint2*>(hh + (size_t)row * HH));   // self
    for (int t0 = 0; t0 < cnt; t0 += 32) {
        int j = (t0 + lane < cnt) ? nbr[t0 + lane] : 0;
        int m = min(32, cnt - t0);
        if (m == 32) {
            #pragma unroll
            for (int kk = 0; kk < 32; kk += 8) {
                int jj[8];
                #pragma unroll
                for (int e = 0; e < 8; e++) jj[e] = __shfl_sync(0xFFFFFFFFu, j, kk + e);
                uint2 r[8];
                #pragma unroll
                for (int e = 0; e < 8; e++)
                    r[e] = *reinterpret_cast<const uint2*>(hh + (size_t)jj[e] * HH);
                #pragma unroll
                for (int e = 0; e < 8; e++) acc_h2x2(acc, r[e]);
            }
        } else {
            for (int k = 0; k < m; k++) {
                int jj = __shfl_sync(0xFFFFFFFFu, j, k);
                uint2 r = *reinterpret_cast<const uint2*>(hh + (size_t)jj * HH);
                acc_h2x2(acc, r);
            }
        }
    }
    float s = g_dis[row];
    __half2 h0 = __float22half2_rn(make_float2(acc.x * s, acc.y * s));
    __half2 h1 = __float22half2_rn(make_float2(acc.z * s, acc.w * s));
    uint2 packed = make_uint2(*reinterpret_cast<uint32_t*>(&h0), *reinterpret_cast<uint32_t*>(&h1));
    *reinterpret_cast<uint2*>(g_agg2h + (size_t)row * HH + half * 128 + lane * 4) = packed;
}

// ---------------- HMMA GEMM, double-buffered cp.async: 128x128 tile, 8 warps, BK=32 ----------------
template <int K, bool SCALE>
__global__ void __launch_bounds__(256, 2) hgemm_kernel(const __half* __restrict__ A,
                                                       const __half* __restrict__ W,
                                                       const float* __restrict__ bias,
                                                       __half* __restrict__ Ch) {
    __shared__ __half As[2][128][40];
    __shared__ __half Bs[2][32][136];

    const int tid  = threadIdx.x;
    const int lane = tid & 31;
    const int warp = tid >> 5;
    const int wm = warp & 3;
    const int wn = warp >> 2;
    const int rowBase = blockIdx.y * 128;
    const int colBase = blockIdx.x * 128;
    const int NITER = K / 32;

    float acc[2][8][4];
    #pragma unroll
    for (int f = 0; f < 2; f++)
        #pragma unroll
        for (int t = 0; t < 8; t++)
            #pragma unroll
            for (int c = 0; c < 4; c++) acc[f][t][c] = 0.f;

    const int ar = tid >> 1, ac = (tid & 1) * 16;
    const int br = tid >> 3, bc = (tid & 7) * 16;

    auto load_tile = [&](int it, int buf) {
        const __half* ag = A + (size_t)(rowBase + ar) * K + it * 32 + ac;
        cp_async16(&As[buf][ar][ac],     ag);
        cp_async16(&As[buf][ar][ac + 8], ag + 8);
        const __half* bg = W + (size_t)(it * 32 + br) * 256 + colBase + bc;
        cp_async16(&Bs[buf][br][bc],     bg);
        cp_async16(&Bs[buf][br][bc + 8], bg + 8);
        cp_commit();
    };

    load_tile(0, 0);
    cp_wait<0>();
    __syncthreads();

    for (int it = 0; it < NITER; it++) {
        int buf = it & 1;
        if (it + 1 < NITER) load_tile(it + 1, (it + 1) & 1);

        #pragma unroll
        for (int kk = 0; kk < 32; kk += 16) {
            uint32_t afr[2][4];
            #pragma unroll
            for (int f = 0; f < 2; f++)
                ldsm_x4(afr[f], cvta_smem(&As[buf][wm * 32 + f * 16 + (lane & 15)][kk + (lane >> 4) * 8]));
            uint32_t bfr[8][2];
            #pragma unroll
            for (int g = 0; g < 4; g++) {
                uint32_t t4[4];
                ldsm_x4_t(t4, cvta_smem(&Bs[buf][kk + (lane & 15)][wn * 64 + g * 16 + (lane >> 4) * 8]));
                bfr[2 * g][0] = t4[0]; bfr[2 * g][1] = t4[1];
                bfr[2 * g + 1][0] = t4[2]; bfr[2 * g + 1][1] = t4[3];
            }
            #pragma unroll
            for (int f = 0; f < 2; f++)
                #pragma unroll
                for (int t = 0; t < 8; t++)
                    mma16816(acc[f][t], afr[f], bfr[t][0], bfr[t][1]);
        }

        if (it + 1 < NITER) {
            cp_wait<0>();
            __syncthreads();
        }
    }

    #pragma unroll
    for (int f = 0; f < 2; f++) {
        #pragma unroll
        for (int t = 0; t < 8; t++) {
            int r0  = rowBase + wm * 32 + f * 16 + (lane >> 2);
            int col = colBase + wn * 64 + t * 8 + (lane & 3) * 2;
            float b0 = bias[col], b1 = bias[col + 1];
            #pragma unroll
            for (int h = 0; h < 2; h++) {
                int row = r0 + h * 8;
                float v0 = fmaxf(acc[f][t][h * 2 + 0] + b0, 0.f);
                float v1 = fmaxf(acc[f][t][h * 2 + 1] + b1, 0.f);
                if (SCALE) { float s = g_dis[row]; v0 *= s; v1 *= s; }
                *reinterpret_cast<__half2*>(Ch + (size_t)row * 256 + col) =
                    __float22half2_rn(make_float2(v0, v1));
            }
        }
    }
}

// ---------------- pooling / classifier + g_cnt reset (64*256 threads == NN) ----------------
__global__ void __launch_bounds__(256) pool_classify_kernel(const float* __restrict__ Wc,
                                                            const float* __restrict__ bc,
                                                            float* __restrict__ out) {
    int g = blockIdx.x;
    int t = threadIdx.x;
    g_cnt[g * 256 + t] = 0;            // restore invariant for the next call
    int s = g_segstart[g], e = g_segstart[g + 1];
    float sum0 = 0.f, sum1 = 0.f;
    int n = s;
    for (; n + 1 < e; n += 2) {
        sum0 += __half2float(g_h2h[(size_t)n * HH + t]);
        sum1 += __half2float(g_h2h[(size_t)(n + 1) * HH + t]);
    }
    if (n < e) sum0 += __half2float(g_h2h[(size_t)n * HH + t]);
    float cnt = (float)max(e - s, 1);
    float pv = (sum0 + sum1) / cnt;

    float part[CC];
    const float* wr = Wc + t * CC;
    #pragma unroll
    for (int c = 0; c < CC; c++) part[c] = pv * wr[c];
    #pragma unroll
    for (int o = 16; o > 0; o >>= 1)
        #pragma unroll
        for (int c = 0; c < CC; c++) part[c] += __shfl_down_sync(0xFFFFFFFFu, part[c], o);

    __shared__ float red[8][CC];
    if ((t & 31) == 0)
        #pragma unroll
        for (int c = 0; c < CC; c++) red[t >> 5][c] = part[c];
    __syncthreads();
    if (t < CC) {
        float o = bc[t];
        #pragma unroll
        for (int w = 0; w < 8; w++) o += red[w][t];
        out[g * CC + t] = o;
    }
}

// ---------------- launch ----------------
extern "C" void kernel_launch(void* const* d_in, const int* in_sizes, int n_in,
                              void* d_out, int out_size) {
    const float* x   = (const float*)d_in[0];
    const int*   ei  = (const int*)  d_in[1];
    const int*   bat = (const int*)  d_in[2];
    const float* W1  = (const float*)d_in[3];
    const float* b1  = (const float*)d_in[4];
    const float* W2  = (const float*)d_in[5];
    const float* b2  = (const float*)d_in[6];
    const float* Wc  = (const float*)d_in[7];
    const float* bc  = (const float*)d_in[8];
    float* out = (float*)d_out;

    __half *w1h, *w2h, *agg1h, *agg2h, *hd1h, *h2h;
    cudaGetSymbolAddress((void**)&w1h,   g_w1h);
    cudaGetSymbolAddress((void**)&w2h,   g_w2h);
    cudaGetSymbolAddress((void**)&agg1h, g_agg1h);
    cudaGetSymbolAddress((void**)&agg2h, g_agg2h);
    cudaGetSymbolAddress((void**)&hd1h,  g_hd1h);
    cudaGetSymbolAddress((void**)&h2h,   g_h2h);

    init_kernel<<<384, 256>>>(W1, W2, bat);
    scatter_build_kernel<<<(EE + 255) / 256, 256>>>(ei);
    finalize_x_kernel<<<2048, 256>>>(x);
    agg1_kernel<<<NN / 8, 256>>>();
    hgemm_kernel<DD, true><<<dim3(2, 128), 256>>>(agg1h, w1h, b1, hd1h);
    agg2_kernel<<<NN / 4, 256>>>();
    hgemm_kernel<HH, false><<<dim3(2, 128), 256>>>(agg2h, w2h, b2, h2h);
    pool_classify_kernel<<<GG, 256>>>(Wc, bc, out);
}

// round 15
// speedup vs baseline: 1.1918x; 1.0216x over previous
#include <cuda_runtime.h>
#include <cuda_fp16.h>
#include <stdint.h>

#define NN      16384
#define EE      524288
#define DD      128
#define HH      256
#define CC      10
#define GG      64
#define WPR     512          // bitmask words per row (16384/32)
#define CAP     160          // max non-self neighbors per row

// ---------------- scratch (device globals; no allocation allowed) ----------------
// INVARIANT: g_bm and g_cnt are all-zero at entry of every kernel_launch call.
// (zero-initialized at module load; agg1 clears bm bits, pool resets cnt.)
__device__ uint32_t g_bm[(size_t)NN * WPR];        // 32 MB adjacency bitmask
__device__ int      g_nbr[(size_t)NN * CAP];       // CSR neighbor lists (unordered, no self)
__device__ int      g_cnt[NN];                     // per-row non-self neighbor counters
__device__ float    g_dis[NN];
__device__ __half   g_xh   [(size_t)NN * DD];      // half(dis[j]*x[j])
__device__ __half   g_agg1h[(size_t)NN * DD];
__device__ __half   g_hd1h [(size_t)NN * HH];      // half(dis*relu(.@W1+b1))
__device__ __half   g_agg2h[(size_t)NN * HH];
__device__ __half   g_h2h  [(size_t)NN * HH];      // half(relu(.@W2+b2))
__device__ __half   g_w1h[DD * HH];
__device__ __half   g_w2h[HH * HH];
__device__ int      g_segstart[GG + 1];

// ---------------- helpers ----------------
__device__ __forceinline__ uint32_t cvta_smem(const void* p) {
    return static_cast<uint32_t>(__cvta_generic_to_shared(p));
}
__device__ __forceinline__ void ldsm_x4(uint32_t (&r)[4], uint32_t addr) {
    asm volatile("ldmatrix.sync.aligned.m8n8.x4.shared.b16 {%0,%1,%2,%3}, [%4];"
                 : "=r"(r[0]), "=r"(r[1]), "=r"(r[2]), "=r"(r[3]) : "r"(addr));
}
__device__ __forceinline__ void ldsm_x4_t(uint32_t (&r)[4], uint32_t addr) {
    asm volatile("ldmatrix.sync.aligned.m8n8.x4.trans.shared.b16 {%0,%1,%2,%3}, [%4];"
                 : "=r"(r[0]), "=r"(r[1]), "=r"(r[2]), "=r"(r[3]) : "r"(addr));
}
__device__ __forceinline__ void mma16816(float (&d)[4], const uint32_t (&a)[4],
                                         const uint32_t b0, const uint32_t b1) {
    asm volatile("mma.sync.aligned.m16n8k16.row.col.f32.f16.f16.f32 "
                 "{%0,%1,%2,%3},{%4,%5,%6,%7},{%8,%9},{%0,%1,%2,%3};"
                 : "+f"(d[0]), "+f"(d[1]), "+f"(d[2]), "+f"(d[3])
                 : "r"(a[0]), "r"(a[1]), "r"(a[2]), "r"(a[3]), "r"(b0), "r"(b1));
}
__device__ __forceinline__ void cp_async16(void* smem, const void* gmem) {
    asm volatile("cp.async.cg.shared.global [%0], [%1], 16;"
                 :: "r"(cvta_smem(smem)), "l"(gmem));
}
__device__ __forceinline__ void cp_commit() {
    asm volatile("cp.async.commit_group;");
}
template <int N>
__device__ __forceinline__ void cp_wait() {
    asm volatile("cp.async.wait_group %0;" :: "n"(N));
}
__device__ __forceinline__ void acc_h2x2(float4& acc, uint2 raw) {
    float2 f0 = __half22float2(*reinterpret_cast<__half2*>(&raw.x));
    float2 f1 = __half22float2(*reinterpret_cast<__half2*>(&raw.y));
    acc.x += f0.x; acc.y += f0.y; acc.z += f1.x; acc.w += f1.y;
}

// ---------------- fused scatter + init: CSR build, weight convert, segstart ----------------
__device__ __forceinline__ void scatter_one(int s, int d) {
    if (s == d) return;               // covered by the implicit self-loop
    uint32_t bit = 1u << (d & 31);
    uint32_t old = atomicOr(&g_bm[(size_t)s * WPR + (d >> 5)], bit);
    if (!(old & bit)) {
        int pos = atomicAdd(&g_cnt[s], 1);
        if (pos < CAP) g_nbr[(size_t)s * CAP + pos] = d;
    }
}

__global__ void scatter_init_kernel(const int* __restrict__ ei,
                                    const float* __restrict__ W1,
                                    const float* __restrict__ W2,
                                    const int* __restrict__ batch) {
    int gidx = blockIdx.x * blockDim.x + threadIdx.x;   // 1024*256 = 262144 = EE/2
    // independent init work (weights, segstart)
    if (gidx < DD * HH) g_w1h[gidx] = __float2half_rn(W1[gidx]);
    if (gidx < HH * HH) g_w2h[gidx] = __float2half_rn(W2[gidx]);
    int g = gidx - 100000;
    if (g >= 0 && g <= GG) {
        if (g == GG) { g_segstart[GG] = NN; }
        else {
            int lo = 0, hi = NN;
            while (lo < hi) {
                int mid = (lo + hi) >> 1;
                if (batch[mid] < g) lo = mid + 1; else hi = mid;
            }
            g_segstart[g] = lo;
        }
    }
    // two edges per thread
    int2 s2 = reinterpret_cast<const int2*>(ei)[gidx];
    int2 d2 = reinterpret_cast<const int2*>(ei + EE)[gidx];
    scatter_one(s2.x, d2.x);
    scatter_one(s2.y, d2.y);
}

// dis[n] = rsqrt(cnt[n]+1);  xh[n][f] = half(dis[n]*x[n][f])
__global__ void finalize_x_kernel(const float* __restrict__ x) {
    const int n2 = NN * DD / 2;
    const float2* x2 = reinterpret_cast<const float2*>(x);
    __half2* o2 = reinterpret_cast<__half2*>(g_xh);
    for (int i = blockIdx.x * blockDim.x + threadIdx.x; i < n2; i += gridDim.x * blockDim.x) {
        int row = i >> 6;
        float s = rsqrtf((float)(g_cnt[row] + 1));
        if ((i & 63) == 0) g_dis[row] = s;
        float2 v = x2[i];
        o2[i] = __float22half2_rn(make_float2(v.x * s, v.y * s));
    }
}

// ---------------- agg1: warp/row, batch-8 uint2 gather, implicit self, + bm clear ----------------
__global__ void agg1_kernel() {
    int row  = (blockIdx.x * blockDim.x + threadIdx.x) >> 5;
    int lane = threadIdx.x & 31;
    if (row >= NN) return;
    const int* __restrict__ nbr = g_nbr + (size_t)row * CAP;
    int cnt = min(g_cnt[row], CAP);
    const __half* __restrict__ xh = g_xh;
    float4 acc = make_float4(0.f, 0.f, 0.f, 0.f);
    acc_h2x2(acc, *reinterpret_cast<const uint2*>(xh + (size_t)row * DD + lane * 4));  // self
    for (int t0 = 0; t0 < cnt; t0 += 32) {
        int j = (t0 + lane < cnt) ? nbr[t0 + lane] : 0;
        int m = min(32, cnt - t0);
        if (m == 32) {
            #pragma unroll
            for (int kk = 0; kk < 32; kk += 8) {
                int jj[8];
                #pragma unroll
                for (int e = 0; e < 8; e++) jj[e] = __shfl_sync(0xFFFFFFFFu, j, kk + e);
                uint2 r[8];
                #pragma unroll
                for (int e = 0; e < 8; e++)
                    r[e] = *reinterpret_cast<const uint2*>(xh + (size_t)jj[e] * DD + lane * 4);
                #pragma unroll
                for (int e = 0; e < 8; e++) acc_h2x2(acc, r[e]);
            }
        } else {
            for (int k = 0; k < m; k++) {
                int jj = __shfl_sync(0xFFFFFFFFu, j, k);
                uint2 r = *reinterpret_cast<const uint2*>(xh + (size_t)jj * DD + lane * 4);
                acc_h2x2(acc, r);
            }
        }
    }
    float s = g_dis[row];
    __half2 h0 = __float22half2_rn(make_float2(acc.x * s, acc.y * s));
    __half2 h1 = __float22half2_rn(make_float2(acc.z * s, acc.w * s));
    uint2 packed = make_uint2(*reinterpret_cast<uint32_t*>(&h0), *reinterpret_cast<uint32_t*>(&h1));
    *reinterpret_cast<uint2*>(g_agg1h + (size_t)row * DD + lane * 4) = packed;
    // clear this row's bitmask bits (row-private; idempotent stores) -> bm zero for next call
    for (int t = lane; t < cnt; t += 32)
        g_bm[(size_t)row * WPR + (nbr[t] >> 5)] = 0u;
}

// 2 warps per row, H=256: each warp handles 128 halves (4/lane, 8B loads), batch-8
__global__ void agg2_kernel() {
    int gw   = (blockIdx.x * blockDim.x + threadIdx.x) >> 5;
    int lane = threadIdx.x & 31;
    int row  = gw >> 1;
    int half = gw & 1;
    if (row >= NN) return;
    const int* __restrict__ nbr = g_nbr + (size_t)row * CAP;
    int cnt = min(g_cnt[row], CAP);
    const __half* __restrict__ hh = g_hd1h + half * 128 + lane * 4;
    float4 acc = make_float4(0.f, 0.f, 0.f, 0.f);
    acc_h2x2(acc, *reinterpret_cast<const uint2*>(hh + (size_t)row * HH));   // self
    for (int t0 = 0; t0 < cnt; t0 += 32) {
        int j = (t0 + lane < cnt) ? nbr[t0 + lane] : 0;
        int m = min(32, cnt - t0);
        if (m == 32) {
            #pragma unroll
            for (int kk = 0; kk < 32; kk += 8) {
                int jj[8];
                #pragma unroll
                for (int e = 0; e < 8; e++) jj[e] = __shfl_sync(0xFFFFFFFFu, j, kk + e);
                uint2 r[8];
                #pragma unroll
                for (int e = 0; e < 8; e++)
                    r[e] = *reinterpret_cast<const uint2*>(hh + (size_t)jj[e] * HH);
                #pragma unroll
                for (int e = 0; e < 8; e++) acc_h2x2(acc, r[e]);
            }
        } else {
            for (int k = 0; k < m; k++) {
                int jj = __shfl_sync(0xFFFFFFFFu, j, k);
                uint2 r = *reinterpret_cast<const uint2*>(hh + (size_t)jj * HH);
                acc_h2x2(acc, r);
            }
        }
    }
    float s = g_dis[row];
    __half2 h0 = __float22half2_rn(make_float2(acc.x * s, acc.y * s));
    __half2 h1 = __float22half2_rn(make_float2(acc.z * s, acc.w * s));
    uint2 packed = make_uint2(*reinterpret_cast<uint32_t*>(&h0), *reinterpret_cast<uint32_t*>(&h1));
    *reinterpret_cast<uint2*>(g_agg2h + (size_t)row * HH + half * 128 + lane * 4) = packed;
}

// ---------------- HMMA GEMM, double-buffered cp.async: 128x128 tile, 8 warps, BK=32 ----------------
template <int K, bool SCALE>
__global__ void __launch_bounds__(256, 2) hgemm_kernel(const __half* __restrict__ A,
                                                       const __half* __restrict__ W,
                                                       const float* __restrict__ bias,
                                                       __half* __restrict__ Ch) {
    __shared__ __half As[2][128][40];
    __shared__ __half Bs[2][32][136];

    const int tid  = threadIdx.x;
    const int lane = tid & 31;
    const int warp = tid >> 5;
    const int wm = warp & 3;
    const int wn = warp >> 2;
    const int rowBase = blockIdx.y * 128;
    const int colBase = blockIdx.x * 128;
    const int NITER = K / 32;

    float acc[2][8][4];
    #pragma unroll
    for (int f = 0; f < 2; f++)
        #pragma unroll
        for (int t = 0; t < 8; t++)
            #pragma unroll
            for (int c = 0; c < 4; c++) acc[f][t][c] = 0.f;

    const int ar = tid >> 1, ac = (tid & 1) * 16;
    const int br = tid >> 3, bc = (tid & 7) * 16;

    auto load_tile = [&](int it, int buf) {
        const __half* ag = A + (size_t)(rowBase + ar) * K + it * 32 + ac;
        cp_async16(&As[buf][ar][ac],     ag);
        cp_async16(&As[buf][ar][ac + 8], ag + 8);
        const __half* bg = W + (size_t)(it * 32 + br) * 256 + colBase + bc;
        cp_async16(&Bs[buf][br][bc],     bg);
        cp_async16(&Bs[buf][br][bc + 8], bg + 8);
        cp_commit();
    };

    load_tile(0, 0);
    cp_wait<0>();
    __syncthreads();

    for (int it = 0; it < NITER; it++) {
        int buf = it & 1;
        if (it + 1 < NITER) load_tile(it + 1, (it + 1) & 1);

        #pragma unroll
        for (int kk = 0; kk < 32; kk += 16) {
            uint32_t afr[2][4];
            #pragma unroll
            for (int f = 0; f < 2; f++)
                ldsm_x4(afr[f], cvta_smem(&As[buf][wm * 32 + f * 16 + (lane & 15)][kk + (lane >> 4) * 8]));
            uint32_t bfr[8][2];
            #pragma unroll
            for (int g = 0; g < 4; g++) {
                uint32_t t4[4];
                ldsm_x4_t(t4, cvta_smem(&Bs[buf][kk + (lane & 15)][wn * 64 + g * 16 + (lane >> 4) * 8]));
                bfr[2 * g][0] = t4[0]; bfr[2 * g][1] = t4[1];
                bfr[2 * g + 1][0] = t4[2]; bfr[2 * g + 1][1] = t4[3];
            }
            #pragma unroll
            for (int f = 0; f < 2; f++)
                #pragma unroll
                for (int t = 0; t < 8; t++)
                    mma16816(acc[f][t], afr[f], bfr[t][0], bfr[t][1]);
        }

        if (it + 1 < NITER) {
            cp_wait<0>();
            __syncthreads();
        }
    }

    #pragma unroll
    for (int f = 0; f < 2; f++) {
        #pragma unroll
        for (int t = 0; t < 8; t++) {
            int r0  = rowBase + wm * 32 + f * 16 + (lane >> 2);
            int col = colBase + wn * 64 + t * 8 + (lane & 3) * 2;
            float b0 = bias[col], b1 = bias[col + 1];
            #pragma unroll
            for (int h = 0; h < 2; h++) {
                int row = r0 + h * 8;
                float v0 = fmaxf(acc[f][t][h * 2 + 0] + b0, 0.f);
                float v1 = fmaxf(acc[f][t][h * 2 + 1] + b1, 0.f);
                if (SCALE) { float s = g_dis[row]; v0 *= s; v1 *= s; }
                *reinterpret_cast<__half2*>(Ch + (size_t)row * 256 + col) =
                    __float22half2_rn(make_float2(v0, v1));
            }
        }
    }
}

// ---------------- pooling / classifier + g_cnt reset (64*256 threads == NN) ----------------
__global__ void __launch_bounds__(256) pool_classify_kernel(const float* __restrict__ Wc,
                                                            const float* __restrict__ bc,
                                                            float* __restrict__ out) {
    int g = blockIdx.x;
    int t = threadIdx.x;
    g_cnt[g * 256 + t] = 0;            // restore invariant for the next call
    int s = g_segstart[g], e = g_segstart[g + 1];
    float sum0 = 0.f, sum1 = 0.f;
    int n = s;
    for (; n + 1 < e; n += 2) {
        sum0 += __half2float(g_h2h[(size_t)n * HH + t]);
        sum1 += __half2float(g_h2h[(size_t)(n + 1) * HH + t]);
    }
    if (n < e) sum0 += __half2float(g_h2h[(size_t)n * HH + t]);
    float cnt = (float)max(e - s, 1);
    float pv = (sum0 + sum1) / cnt;

    float part[CC];
    const float* wr = Wc + t * CC;
    #pragma unroll
    for (int c = 0; c < CC; c++) part[c] = pv * wr[c];
    #pragma unroll
    for (int o = 16; o > 0; o >>= 1)
        #pragma unroll
        for (int c = 0; c < CC; c++) part[c] += __shfl_down_sync(0xFFFFFFFFu, part[c], o);

    __shared__ float red[8][CC];
    if ((t & 31) == 0)
        #pragma unroll
        for (int c = 0; c < CC; c++) red[t >> 5][c] = part[c];
    __syncthreads();
    if (t < CC) {
        float o = bc[t];
        #pragma unroll
        for (int w = 0; w < 8; w++) o += red[w][t];
        out[g * CC + t] = o;
    }
}

// ---------------- launch ----------------
extern "C" void kernel_launch(void* const* d_in, const int* in_sizes, int n_in,
                              void* d_out, int out_size) {
    const float* x   = (const float*)d_in[0];
    const int*   ei  = (const int*)  d_in[1];
    const int*   bat = (const int*)  d_in[2];
    const float* W1  = (const float*)d_in[3];
    const float* b1  = (const float*)d_in[4];
    const float* W2  = (const float*)d_in[5];
    const float* b2  = (const float*)d_in[6];
    const float* Wc  = (const float*)d_in[7];
    const float* bc  = (const float*)d_in[8];
    float* out = (float*)d_out;

    __half *w1h, *w2h, *agg1h, *agg2h, *hd1h, *h2h;
    cudaGetSymbolAddress((void**)&w1h,   g_w1h);
    cudaGetSymbolAddress((void**)&w2h,   g_w2h);
    cudaGetSymbolAddress((void**)&agg1h, g_agg1h);
    cudaGetSymbolAddress((void**)&agg2h, g_agg2h);
    cudaGetSymbolAddress((void**)&hd1h,  g_hd1h);
    cudaGetSymbolAddress((void**)&h2h,   g_h2h);

    scatter_init_kernel<<<EE / 2 / 256, 256>>>(ei, W1, W2, bat);
    finalize_x_kernel<<<2048, 256>>>(x);
    agg1_kernel<<<NN / 8, 256>>>();
    hgemm_kernel<DD, true><<<dim3(2, 128), 256>>>(agg1h, w1h, b1, hd1h);
    agg2_kernel<<<NN / 4, 256>>>();
    hgemm_kernel<HH, false><<<dim3(2, 128), 256>>>(agg2h, w2h, b2, h2h);
    pool_classify_kernel<<<GG, 256>>>(Wc, bc, out);
}